// round 1
// baseline (speedup 1.0000x reference)
#include <cuda_runtime.h>
#include <math.h>
#include <stdint.h>

// ---------------- problem constants ----------------
#define NN 20000        // nodes
#define EE 320000       // edges
#define MEM 128
#define INC 256         // in_channels = H*C
#define HH 2
#define CC 128
#define ED 200          // edge dim (100 time + 100 msg)
#define TD 100
#define NLAYER 3

static __device__ __constant__ float RSQRT_C = 0.08838834764831845f; // 1/sqrt(128)

// ---------------- scratch (static device allocations; allowed) ----------------
__device__ float g_eattr[(size_t)EE * ED];     // 256 MB
__device__ float g_h   [(size_t)NN * INC];
__device__ float g_q   [(size_t)NN * INC];
__device__ float g_k   [(size_t)NN * INC];
__device__ float g_v   [(size_t)NN * INC];
__device__ float g_sk  [(size_t)NN * INC];
__device__ float g_U   [(size_t)NN * 2 * ED];
__device__ float g_s   [(size_t)NN * 2 * ED];
__device__ float g_agg [(size_t)NN * INC];
__device__ float g_alpha[(size_t)EE * 2];
__device__ int   g_deg [NN];
__device__ int   g_cnt [NN];
__device__ int   g_rowptr[NN + 1];
__device__ int   g_eid [EE];

// ---------------- CSR construction ----------------
__global__ void k_zero_int() {
    int i = blockIdx.x * blockDim.x + threadIdx.x;
    if (i < NN) { g_deg[i] = 0; g_cnt[i] = 0; }
}
__global__ void k_count(const int* __restrict__ dst) {
    int e = blockIdx.x * blockDim.x + threadIdx.x;
    if (e < EE) atomicAdd(&g_deg[dst[e]], 1);
}
// single-block inclusive scan -> rowptr
__global__ void k_scan() {
    __shared__ int sm[1024];
    int tid = threadIdx.x;
    int carry = 0;
    for (int base = 0; base < NN; base += 1024) {
        int i = base + tid;
        int v = (i < NN) ? g_deg[i] : 0;
        sm[tid] = v;
        __syncthreads();
        for (int off = 1; off < 1024; off <<= 1) {
            int x = (tid >= off) ? sm[tid - off] : 0;
            __syncthreads();
            sm[tid] += x;
            __syncthreads();
        }
        if (i < NN) g_rowptr[i + 1] = carry + sm[tid];
        int total = sm[1023];
        __syncthreads();
        carry += total;
    }
    if (tid == 0) g_rowptr[0] = 0;
}
__global__ void k_place(const int* __restrict__ dst) {
    int e = blockIdx.x * blockDim.x + threadIdx.x;
    if (e < EE) {
        int d = dst[e];
        int p = atomicAdd(&g_cnt[d], 1);
        g_eid[g_rowptr[d] + p] = e;
    }
}

// ---------------- edge features ----------------
__global__ void k_eattr(const int* __restrict__ src,
                        const float* __restrict__ last_update,
                        const float* __restrict__ t,
                        const float* __restrict__ msg,
                        const float* __restrict__ time_w,
                        const float* __restrict__ time_b) {
    long long idx = (long long)blockIdx.x * blockDim.x + threadIdx.x;
    long long total = (long long)EE * ED;
    if (idx >= total) return;
    int e = (int)(idx / ED);
    int j = (int)(idx - (long long)e * ED);
    float val;
    if (j < TD) {
        float rt = last_update[src[e]] - t[e];
        val = cosf(rt * time_w[j] + time_b[j]);
    } else {
        val = msg[(size_t)e * 100 + (j - TD)];
    }
    g_eattr[idx] = val;
}

// ---------------- generic tiled SGEMM (128x128x16, 8x8/thread, 256 thr) ----------------
template<bool TRANSB, bool ACCUM, bool BIAS>
__global__ void sgemm_k(int M, int N, int K,
                        const float* __restrict__ A, int lda,
                        const float* __restrict__ B, int ldb,
                        const float* __restrict__ bias,
                        float* __restrict__ C, int ldc) {
    constexpr int BM = 128, BN = 128, BK = 16;
    __shared__ float As[BK][BM + 4];   // pad 4 keeps 16B alignment of rows
    __shared__ float Bs[BK][BN];
    int tid = threadIdx.x;
    int tx = tid & 15;     // col group
    int ty = tid >> 4;     // row group
    int m0 = blockIdx.y * BM;
    int n0 = blockIdx.x * BN;

    float acc[8][8];
#pragma unroll
    for (int i = 0; i < 8; i++)
#pragma unroll
        for (int j = 0; j < 8; j++) acc[i][j] = 0.f;

    for (int k0 = 0; k0 < K; k0 += BK) {
        // load A tile (BM x BK), coalesced along k, store transposed
#pragma unroll
        for (int it = 0; it < (BM * BK) / 256; it++) {
            int idx = tid + it * 256;
            int m = idx >> 4, kk = idx & 15;
            int gm = m0 + m, gk = k0 + kk;
            As[kk][m] = (gm < M && gk < K) ? A[(size_t)gm * lda + gk] : 0.f;
        }
        // load B tile (BK x BN)
#pragma unroll
        for (int it = 0; it < (BK * BN) / 256; it++) {
            int idx = tid + it * 256;
            int kk = idx >> 7, n = idx & 127;
            int gk = k0 + kk, gn = n0 + n;
            float v = 0.f;
            if (gk < K && gn < N)
                v = TRANSB ? B[(size_t)gn * ldb + gk] : B[(size_t)gk * ldb + gn];
            Bs[kk][n] = v;
        }
        __syncthreads();
#pragma unroll
        for (int kk = 0; kk < BK; kk++) {
            float4 a0 = *(const float4*)&As[kk][ty * 8];
            float4 a1 = *(const float4*)&As[kk][ty * 8 + 4];
            float4 b0 = *(const float4*)&Bs[kk][tx * 8];
            float4 b1 = *(const float4*)&Bs[kk][tx * 8 + 4];
            float av[8] = {a0.x, a0.y, a0.z, a0.w, a1.x, a1.y, a1.z, a1.w};
            float bv[8] = {b0.x, b0.y, b0.z, b0.w, b1.x, b1.y, b1.z, b1.w};
#pragma unroll
            for (int i = 0; i < 8; i++)
#pragma unroll
                for (int j = 0; j < 8; j++) acc[i][j] += av[i] * bv[j];
        }
        __syncthreads();
    }
#pragma unroll
    for (int i = 0; i < 8; i++) {
        int gm = m0 + ty * 8 + i;
        if (gm >= M) continue;
#pragma unroll
        for (int j = 0; j < 8; j++) {
            int gn = n0 + tx * 8 + j;
            if (gn >= N) continue;
            float r = acc[i][j];
            if (BIAS) r += bias[gn];
            size_t off = (size_t)gm * ldc + gn;
            if (ACCUM) r += C[off];
            C[off] = r;
        }
    }
}

// ---------------- alpha: warp per edge ----------------
__global__ void k_alpha(const int* __restrict__ src, const int* __restrict__ dst) {
    int w = (blockIdx.x * blockDim.x + threadIdx.x) >> 5;
    int lane = threadIdx.x & 31;
    if (w >= EE) return;
    int s = src[w], d = dst[w];
    const float* qr = g_q + (size_t)d * INC;
    const float* kr = g_k + (size_t)s * INC;
    float acc0 = 0.f, acc1 = 0.f;
#pragma unroll
    for (int c = lane; c < CC; c += 32) {
        acc0 += qr[c] * kr[c];
        acc1 += qr[CC + c] * kr[CC + c];
    }
    const float* er = g_eattr + (size_t)w * ED;
    const float* Ur = g_U + (size_t)d * (2 * ED);
    for (int j = lane; j < ED; j += 32) {
        float ev = er[j];
        acc0 += ev * Ur[j];
        acc1 += ev * Ur[ED + j];
    }
#pragma unroll
    for (int o = 16; o; o >>= 1) {
        acc0 += __shfl_xor_sync(0xffffffffu, acc0, o);
        acc1 += __shfl_xor_sync(0xffffffffu, acc1, o);
    }
    if (lane == 0) {
        g_alpha[2 * (size_t)w]     = acc0 * RSQRT_C;
        g_alpha[2 * (size_t)w + 1] = acc1 * RSQRT_C;
    }
}

// ---------------- segment softmax: warp per node ----------------
__global__ void k_softmax() {
    int n = (blockIdx.x * blockDim.x + threadIdx.x) >> 5;
    int lane = threadIdx.x & 31;
    if (n >= NN) return;
    int b = g_rowptr[n], e_ = g_rowptr[n + 1];
    if (b == e_) return;
    float m0 = -3.4e38f, m1 = -3.4e38f;
    for (int j = b + lane; j < e_; j += 32) {
        int e = g_eid[j];
        m0 = fmaxf(m0, g_alpha[2 * (size_t)e]);
        m1 = fmaxf(m1, g_alpha[2 * (size_t)e + 1]);
    }
#pragma unroll
    for (int o = 16; o; o >>= 1) {
        m0 = fmaxf(m0, __shfl_xor_sync(0xffffffffu, m0, o));
        m1 = fmaxf(m1, __shfl_xor_sync(0xffffffffu, m1, o));
    }
    float s0 = 0.f, s1 = 0.f;
    for (int j = b + lane; j < e_; j += 32) {
        int e = g_eid[j];
        s0 += expf(g_alpha[2 * (size_t)e]     - m0);
        s1 += expf(g_alpha[2 * (size_t)e + 1] - m1);
    }
#pragma unroll
    for (int o = 16; o; o >>= 1) {
        s0 += __shfl_xor_sync(0xffffffffu, s0, o);
        s1 += __shfl_xor_sync(0xffffffffu, s1, o);
    }
    float d0 = s0 + 1e-16f, d1 = s1 + 1e-16f;
    for (int j = b + lane; j < e_; j += 32) {
        int e = g_eid[j];
        float a0 = expf(g_alpha[2 * (size_t)e]     - m0) / d0;
        float a1 = expf(g_alpha[2 * (size_t)e + 1] - m1) / d1;
        g_alpha[2 * (size_t)e]     = a0;
        g_alpha[2 * (size_t)e + 1] = a1;
    }
}

// ---------------- aggregation: warp per node -> vagg (g_agg) + s (g_s) ----------------
__global__ void k_agg(const int* __restrict__ src) {
    int n = (blockIdx.x * blockDim.x + threadIdx.x) >> 5;
    int lane = threadIdx.x & 31;
    if (n >= NN) return;
    int b = g_rowptr[n], e_ = g_rowptr[n + 1];
    float vacc[8];
    float sacc[13];
#pragma unroll
    for (int i = 0; i < 8; i++) vacc[i] = 0.f;
#pragma unroll
    for (int i = 0; i < 13; i++) sacc[i] = 0.f;

    for (int j = b; j < e_; j++) {
        int e = g_eid[j];
        int s = src[e];
        float a0 = g_alpha[2 * (size_t)e];
        float a1 = g_alpha[2 * (size_t)e + 1];
        const float* vr = g_v + (size_t)s * INC;
#pragma unroll
        for (int k2 = 0; k2 < 8; k2++) {
            int cc = lane + 32 * k2;
            vacc[k2] += (cc < CC ? a0 : a1) * vr[cc];
        }
        const float* er = g_eattr + (size_t)e * ED;
#pragma unroll
        for (int k2 = 0; k2 < 13; k2++) {
            int dd = lane + 32 * k2;
            if (dd < 2 * ED) {
                int hh = (dd >= ED);
                int d_ = dd - hh * ED;
                sacc[k2] += (hh ? a1 : a0) * er[d_];
            }
        }
    }
    float* ar = g_agg + (size_t)n * INC;
#pragma unroll
    for (int k2 = 0; k2 < 8; k2++) ar[lane + 32 * k2] = vacc[k2];
    float* sr = g_s + (size_t)n * (2 * ED);
#pragma unroll
    for (int k2 = 0; k2 < 13; k2++) {
        int dd = lane + 32 * k2;
        if (dd < 2 * ED) sr[dd] = sacc[k2];
    }
}

// ---------------- residual + LayerNorm (+ SiLU) ----------------
__global__ void k_ln(const float* __restrict__ ln_g, const float* __restrict__ ln_b,
                     float* __restrict__ out, int silu) {
    int n = blockIdx.x;
    int c = threadIdx.x;
    size_t off = (size_t)n * INC + c;
    float pre = g_h[off] + g_agg[off] + g_sk[off];
    __shared__ float red[INC];
    red[c] = pre;
    __syncthreads();
#pragma unroll
    for (int o = 128; o; o >>= 1) {
        if (c < o) red[c] += red[c + o];
        __syncthreads();
    }
    float mu = red[0] * (1.f / INC);
    __syncthreads();
    float dv = pre - mu;
    red[c] = dv * dv;
    __syncthreads();
#pragma unroll
    for (int o = 128; o; o >>= 1) {
        if (c < o) red[c] += red[c + o];
        __syncthreads();
    }
    float var = red[0] * (1.f / INC);
    float y = dv * rsqrtf(var + 1e-5f) * ln_g[c] + ln_b[c];
    if (silu) y = y / (1.f + expf(-y));
    out[off] = y;
}

// ---------------- host launcher ----------------
static inline void get_sym(void** p, const void* sym) {
    cudaGetSymbolAddress(p, sym);
}

extern "C" void kernel_launch(void* const* d_in, const int* in_sizes, int n_in,
                              void* d_out, int out_size) {
    const float* x           = (const float*)d_in[0];
    const float* last_update = (const float*)d_in[1];
    const int*   edge_index  = (const int*)  d_in[2];
    const float* t           = (const float*)d_in[3];
    const float* msg         = (const float*)d_in[4];
    const float* time_w      = (const float*)d_in[5];
    const float* time_b      = (const float*)d_in[6];
    const float* lin_w       = (const float*)d_in[7];
    const float* lin_b       = (const float*)d_in[8];
    const float* Wq          = (const float*)d_in[9];
    const float* bq          = (const float*)d_in[10];
    const float* Wk          = (const float*)d_in[11];
    const float* bk          = (const float*)d_in[12];
    const float* Wv          = (const float*)d_in[13];
    const float* bv          = (const float*)d_in[14];
    const float* We          = (const float*)d_in[15];
    const float* Wsk         = (const float*)d_in[16];
    const float* bsk         = (const float*)d_in[17];
    const float* ln_g        = (const float*)d_in[18];
    const float* ln_b        = (const float*)d_in[19];

    const int* src = edge_index;
    const int* dst = edge_index + EE;

    float *p_h, *p_q, *p_k, *p_v, *p_sk, *p_U, *p_s, *p_agg;
    get_sym((void**)&p_h,   g_h);
    get_sym((void**)&p_q,   g_q);
    get_sym((void**)&p_k,   g_k);
    get_sym((void**)&p_v,   g_v);
    get_sym((void**)&p_sk,  g_sk);
    get_sym((void**)&p_U,   g_U);
    get_sym((void**)&p_s,   g_s);
    get_sym((void**)&p_agg, g_agg);

    // ---- CSR build ----
    k_zero_int<<<(NN + 255) / 256, 256>>>();
    k_count<<<(EE + 255) / 256, 256>>>(dst);
    k_scan<<<1, 1024>>>();
    k_place<<<(EE + 255) / 256, 256>>>(dst);

    // ---- edge features ----
    {
        long long total = (long long)EE * ED;
        int blocks = (int)((total + 255) / 256);
        k_eattr<<<blocks, 256>>>(src, last_update, t, msg, time_w, time_b);
    }

    // ---- h0 = x @ lin_w + lin_b ----
    {
        dim3 grid((INC + 127) / 128, (NN + 127) / 128);
        sgemm_k<false, false, true><<<grid, 256>>>(NN, INC, MEM, x, MEM, lin_w, INC,
                                                   lin_b, p_h, INC);
    }

    for (int L = 0; L < NLAYER; L++) {
        const float* Wq_i = Wq + (size_t)L * INC * INC;
        const float* Wk_i = Wk + (size_t)L * INC * INC;
        const float* Wv_i = Wv + (size_t)L * INC * INC;
        const float* Ws_i = Wsk + (size_t)L * INC * INC;
        const float* We_i = We + (size_t)L * ED * INC;
        const float* bq_i = bq + (size_t)L * INC;
        const float* bk_i = bk + (size_t)L * INC;
        const float* bv_i = bv + (size_t)L * INC;
        const float* bs_i = bsk + (size_t)L * INC;

        dim3 gqkv((INC + 127) / 128, (NN + 127) / 128);
        sgemm_k<false, false, true><<<gqkv, 256>>>(NN, INC, INC, p_h, INC, Wq_i, INC, bq_i, p_q, INC);
        sgemm_k<false, false, true><<<gqkv, 256>>>(NN, INC, INC, p_h, INC, Wk_i, INC, bk_i, p_k, INC);
        sgemm_k<false, false, true><<<gqkv, 256>>>(NN, INC, INC, p_h, INC, Wv_i, INC, bv_i, p_v, INC);
        sgemm_k<false, false, true><<<gqkv, 256>>>(NN, INC, INC, p_h, INC, Ws_i, INC, bs_i, p_sk, INC);

        // U[n,h,:] = q[n,h,:] @ We_h^T  (M=NN, N=ED, K=CC), per head
        {
            dim3 gu((ED + 127) / 128, (NN + 127) / 128);
            for (int h = 0; h < HH; h++) {
                sgemm_k<true, false, false><<<gu, 256>>>(
                    NN, ED, CC,
                    p_q + h * CC, INC,
                    We_i + h * CC, INC,
                    nullptr,
                    p_U + h * ED, 2 * ED);
            }
        }

        k_alpha<<<(EE * 32 + 255) / 256, 256>>>(src, dst);
        k_softmax<<<(NN * 32 + 255) / 256, 256>>>();
        k_agg<<<(NN * 32 + 255) / 256, 256>>>(src);

        // agg += s[n,h,:] @ We_h  (M=NN, N=CC, K=ED), per head, accumulate onto vagg
        {
            dim3 gs((CC + 127) / 128, (NN + 127) / 128);
            for (int h = 0; h < HH; h++) {
                sgemm_k<false, true, false><<<gs, 256>>>(
                    NN, CC, ED,
                    p_s + h * ED, 2 * ED,
                    We_i + h * CC, INC,
                    nullptr,
                    p_agg + h * CC, INC);
            }
        }

        float* out_ptr = (L == NLAYER - 1) ? (float*)d_out : p_h;
        k_ln<<<NN, INC>>>(ln_g + (size_t)L * INC, ln_b + (size_t)L * INC,
                          out_ptr, (L < NLAYER - 1) ? 1 : 0);
    }
}

// round 3
// speedup vs baseline: 1.5991x; 1.5991x over previous
#include <cuda_runtime.h>
#include <cuda_bf16.h>
#include <math.h>
#include <stdint.h>

// ---------------- problem constants ----------------
#define NN 20000
#define EE 320000
#define MEM 128
#define INC 256
#define HH 2
#define CC 128
#define ED 200
#define TD 100
#define NLAYER 3

static __device__ __constant__ float RSQRT_C = 0.08838834764831845f; // 1/sqrt(128)

// ---------------- scratch ----------------
__device__ float g_eattr[(size_t)EE * ED];       // 256 MB
__device__ float g_h    [(size_t)NN * INC];
__device__ float g_qkvs [(size_t)NN * 1024];     // q|k|v|sk packed
__device__ float g_U    [(size_t)NN * 2 * ED];
__device__ float g_s    [(size_t)NN * 2 * ED];
__device__ float g_agg  [(size_t)NN * INC];
__device__ float g_alpha[(size_t)EE * 2];
__device__ int   g_deg [NN];
__device__ int   g_cnt [NN];
__device__ int   g_rowptr[NN + 1];
__device__ int   g_eid [EE];
// packed / transposed weights
__device__ float g_WTpack[(size_t)NLAYER * 1024 * 256];  // [L][n(q,k,v,sk)][k]
__device__ float g_bpack [(size_t)NLAYER * 1024];
__device__ float g_linT  [(size_t)256 * 128];            // lin_w^T
__device__ float g_WeT   [(size_t)NLAYER * 256 * 200];   // We^T: [L][c][j]

// ---------------- bf16 split helpers ----------------
__device__ __forceinline__ uint32_t pack_hi(float x, float y) {
    __nv_bfloat162 p = __floats2bfloat162_rn(x, y);
    return *(uint32_t*)&p;
}
__device__ __forceinline__ uint32_t pack_mid(float x, float y) {
    __nv_bfloat16 hx = __float2bfloat16(x);
    __nv_bfloat16 hy = __float2bfloat16(y);
    __nv_bfloat162 p = __floats2bfloat162_rn(x - __bfloat162float(hx),
                                             y - __bfloat162float(hy));
    return *(uint32_t*)&p;
}

__device__ __forceinline__ void mma_bf16(float* c, const uint32_t* a,
                                         uint32_t b0, uint32_t b1) {
    asm volatile(
        "mma.sync.aligned.m16n8k16.row.col.f32.bf16.bf16.f32 "
        "{%0,%1,%2,%3}, {%4,%5,%6,%7}, {%8,%9}, {%0,%1,%2,%3};"
        : "+f"(c[0]), "+f"(c[1]), "+f"(c[2]), "+f"(c[3])
        : "r"(a[0]), "r"(a[1]), "r"(a[2]), "r"(a[3]), "r"(b0), "r"(b1));
}

// ---------------- HMMA 3xBF16 GEMM: C[M,N] (+)= A[M,K] @ B^T[N,K] ----------------
// A row-major [M,lda]; B row-major [N,ldb] (holds B[n,k]); optional bias[n]; optional accum.
// Block tile 128x128, BK=32, 256 threads (8 warps, 4 m x 2 n), single-buffered SMEM.
#define PADU 17   // uint32 (bf16 pair) stride per row: 16 pairs + 1 pad

__global__ __launch_bounds__(256, 1)
void tc_gemm(int M, int N, int K,
             const float* __restrict__ A, int lda,
             const float* __restrict__ B, int ldb,
             const float* __restrict__ bias,
             float* __restrict__ C, int ldc,
             int accum) {
    __shared__ uint32_t As_h[128 * PADU];
    __shared__ uint32_t As_m[128 * PADU];
    __shared__ uint32_t Bs_h[128 * PADU];
    __shared__ uint32_t Bs_m[128 * PADU];

    const int tid = threadIdx.x;
    const int wid = tid >> 5;
    const int lane = tid & 31;
    const int wm = wid & 3;      // 0..3, 32 rows each
    const int wn = wid >> 2;     // 0..1, 64 cols each
    const int m0 = blockIdx.y * 128;
    const int n0 = blockIdx.x * 128;

    float c[2][8][4];
#pragma unroll
    for (int i = 0; i < 2; i++)
#pragma unroll
        for (int j = 0; j < 8; j++)
#pragma unroll
            for (int l = 0; l < 4; l++) c[i][j][l] = 0.f;

    const int nc = (K + 31) >> 5;
    for (int ch = 0; ch < nc; ch++) {
        const int k0 = ch << 5;
        // ---- load A chunk [128 x 32] fp32 -> (hi, mid) bf16 pairs ----
#pragma unroll
        for (int it = 0; it < 4; it++) {
            int id = tid + it * 256;
            int r = id >> 3, c4 = (id & 7) * 4;
            int gm = m0 + r, gk = k0 + c4;
            float4 v = make_float4(0.f, 0.f, 0.f, 0.f);
            if (gm < M && gk < K) v = *(const float4*)(A + (size_t)gm * lda + gk);
            int base = r * PADU + (c4 >> 1);
            As_h[base]     = pack_hi(v.x, v.y);
            As_h[base + 1] = pack_hi(v.z, v.w);
            As_m[base]     = pack_mid(v.x, v.y);
            As_m[base + 1] = pack_mid(v.z, v.w);
        }
        // ---- load B chunk [128 x 32] ----
#pragma unroll
        for (int it = 0; it < 4; it++) {
            int id = tid + it * 256;
            int r = id >> 3, c4 = (id & 7) * 4;
            int gn = n0 + r, gk = k0 + c4;
            float4 v = make_float4(0.f, 0.f, 0.f, 0.f);
            if (gn < N && gk < K) v = *(const float4*)(B + (size_t)gn * ldb + gk);
            int base = r * PADU + (c4 >> 1);
            Bs_h[base]     = pack_hi(v.x, v.y);
            Bs_h[base + 1] = pack_hi(v.z, v.w);
            Bs_m[base]     = pack_mid(v.x, v.y);
            Bs_m[base + 1] = pack_mid(v.z, v.w);
        }
        __syncthreads();

#pragma unroll
        for (int ks = 0; ks < 2; ks++) {
            const int kp = ks * 8;
            const int kc = kp + (lane & 3);
            uint32_t ah[2][4], am[2][4];
#pragma unroll
            for (int mt = 0; mt < 2; mt++) {
                int r0 = (wm * 32 + mt * 16 + (lane >> 2)) * PADU;
                int r1 = r0 + 8 * PADU;
                ah[mt][0] = As_h[r0 + kc];
                ah[mt][1] = As_h[r1 + kc];
                ah[mt][2] = As_h[r0 + kc + 4];
                ah[mt][3] = As_h[r1 + kc + 4];
                am[mt][0] = As_m[r0 + kc];
                am[mt][1] = As_m[r1 + kc];
                am[mt][2] = As_m[r0 + kc + 4];
                am[mt][3] = As_m[r1 + kc + 4];
            }
#pragma unroll
            for (int nt = 0; nt < 8; nt++) {
                int nb = (wn * 64 + nt * 8 + (lane >> 2)) * PADU;
                uint32_t bh0 = Bs_h[nb + kc];
                uint32_t bh1 = Bs_h[nb + kc + 4];
                uint32_t bm0 = Bs_m[nb + kc];
                uint32_t bm1 = Bs_m[nb + kc + 4];
#pragma unroll
                for (int mt = 0; mt < 2; mt++) {
                    mma_bf16(c[mt][nt], ah[mt], bh0, bh1);
                    mma_bf16(c[mt][nt], ah[mt], bm0, bm1);
                    mma_bf16(c[mt][nt], am[mt], bh0, bh1);
                }
            }
        }
        __syncthreads();
    }

    // ---- epilogue ----
#pragma unroll
    for (int mt = 0; mt < 2; mt++) {
        int row0 = m0 + wm * 32 + mt * 16 + (lane >> 2);
#pragma unroll
        for (int nt = 0; nt < 8; nt++) {
            int col = n0 + wn * 64 + nt * 8 + 2 * (lane & 3);
            if (col >= N) continue;
#pragma unroll
            for (int half = 0; half < 2; half++) {
                int row = row0 + 8 * half;
                if (row >= M) continue;
                float v0 = c[mt][nt][2 * half];
                float v1 = c[mt][nt][2 * half + 1];
                if (bias) { v0 += bias[col]; v1 += (col + 1 < N) ? bias[col + 1] : 0.f; }
                size_t off = (size_t)row * ldc + col;
                if (accum) {
                    v0 += C[off];
                    if (col + 1 < N) v1 += C[off + 1];
                }
                C[off] = v0;
                if (col + 1 < N) C[off + 1] = v1;
            }
        }
    }
}

// ---------------- weight prep (transpose/pack), once per call ----------------
__global__ void k_prep(const float* __restrict__ Wq, const float* __restrict__ Wk,
                       const float* __restrict__ Wv, const float* __restrict__ Wsk,
                       const float* __restrict__ bq, const float* __restrict__ bk,
                       const float* __restrict__ bv, const float* __restrict__ bsk,
                       const float* __restrict__ lin_w, const float* __restrict__ We) {
    const int A1 = NLAYER * 1024 * 256;
    const int A2 = NLAYER * 1024;
    const int A3 = 256 * 128;
    const int A4 = NLAYER * 256 * 200;
    int total = A1 + A2 + A3 + A4;
    for (int idx = blockIdx.x * blockDim.x + threadIdx.x; idx < total;
         idx += gridDim.x * blockDim.x) {
        if (idx < A1) {
            int L = idx / (1024 * 256);
            int rem = idx - L * 1024 * 256;
            int row = rem >> 8;
            int k = rem & 255;
            int which = row >> 8;
            int n = row & 255;
            const float* W = (which == 0) ? Wq : (which == 1) ? Wk : (which == 2) ? Wv : Wsk;
            g_WTpack[idx] = W[(size_t)L * 65536 + (size_t)k * 256 + n];
        } else if (idx < A1 + A2) {
            int i2 = idx - A1;
            int L = i2 / 1024;
            int row = i2 - L * 1024;
            int which = row >> 8;
            int n = row & 255;
            const float* bb = (which == 0) ? bq : (which == 1) ? bk : (which == 2) ? bv : bsk;
            g_bpack[i2] = bb[L * 256 + n];
        } else if (idx < A1 + A2 + A3) {
            int i3 = idx - A1 - A2;
            int n = i3 >> 7, k = i3 & 127;
            g_linT[i3] = lin_w[(size_t)k * 256 + n];
        } else {
            int i4 = idx - A1 - A2 - A3;
            int L = i4 / (256 * 200);
            int rem = i4 - L * 256 * 200;
            int c = rem / 200;
            int j = rem - c * 200;
            g_WeT[i4] = We[(size_t)L * 51200 + (size_t)j * 256 + c];
        }
    }
}

// ---------------- CSR construction ----------------
__global__ void k_zero_int() {
    int i = blockIdx.x * blockDim.x + threadIdx.x;
    if (i < NN) { g_deg[i] = 0; g_cnt[i] = 0; }
}
__global__ void k_count(const int* __restrict__ dst) {
    int e = blockIdx.x * blockDim.x + threadIdx.x;
    if (e < EE) atomicAdd(&g_deg[dst[e]], 1);
}
__global__ void k_scan() {
    __shared__ int sm[1024];
    int tid = threadIdx.x;
    int carry = 0;
    for (int base = 0; base < NN; base += 1024) {
        int i = base + tid;
        int v = (i < NN) ? g_deg[i] : 0;
        sm[tid] = v;
        __syncthreads();
        for (int off = 1; off < 1024; off <<= 1) {
            int x = (tid >= off) ? sm[tid - off] : 0;
            __syncthreads();
            sm[tid] += x;
            __syncthreads();
        }
        if (i < NN) g_rowptr[i + 1] = carry + sm[tid];
        int total = sm[1023];
        __syncthreads();
        carry += total;
    }
    if (tid == 0) g_rowptr[0] = 0;
}
__global__ void k_place(const int* __restrict__ dst) {
    int e = blockIdx.x * blockDim.x + threadIdx.x;
    if (e < EE) {
        int d = dst[e];
        int p = atomicAdd(&g_cnt[d], 1);
        g_eid[g_rowptr[d] + p] = e;
    }
}

// ---------------- edge features ----------------
__global__ void k_eattr(const int* __restrict__ src,
                        const float* __restrict__ last_update,
                        const float* __restrict__ t,
                        const float* __restrict__ msg,
                        const float* __restrict__ time_w,
                        const float* __restrict__ time_b) {
    long long idx = (long long)blockIdx.x * blockDim.x + threadIdx.x;
    long long total = (long long)EE * ED;
    if (idx >= total) return;
    int e = (int)(idx / ED);
    int j = (int)(idx - (long long)e * ED);
    float val;
    if (j < TD) {
        float rt = last_update[src[e]] - t[e];
        val = cosf(rt * time_w[j] + time_b[j]);
    } else {
        val = msg[(size_t)e * 100 + (j - TD)];
    }
    g_eattr[idx] = val;
}

// ---------------- alpha: warp per edge ----------------
__global__ void k_alpha(const int* __restrict__ src, const int* __restrict__ dst) {
    int w = (blockIdx.x * blockDim.x + threadIdx.x) >> 5;
    int lane = threadIdx.x & 31;
    if (w >= EE) return;
    int s = src[w], d = dst[w];
    const float* qr = g_qkvs + (size_t)d * 1024;
    const float* kr = g_qkvs + (size_t)s * 1024 + 256;
    float acc0 = 0.f, acc1 = 0.f;
#pragma unroll
    for (int c = lane; c < CC; c += 32) {
        acc0 += qr[c] * kr[c];
        acc1 += qr[CC + c] * kr[CC + c];
    }
    const float* er = g_eattr + (size_t)w * ED;
    const float* Ur = g_U + (size_t)d * (2 * ED);
    for (int j = lane; j < ED; j += 32) {
        float ev = er[j];
        acc0 += ev * Ur[j];
        acc1 += ev * Ur[ED + j];
    }
#pragma unroll
    for (int o = 16; o; o >>= 1) {
        acc0 += __shfl_xor_sync(0xffffffffu, acc0, o);
        acc1 += __shfl_xor_sync(0xffffffffu, acc1, o);
    }
    if (lane == 0) {
        g_alpha[2 * (size_t)w]     = acc0 * RSQRT_C;
        g_alpha[2 * (size_t)w + 1] = acc1 * RSQRT_C;
    }
}

// ---------------- segment softmax: warp per node ----------------
__global__ void k_softmax() {
    int n = (blockIdx.x * blockDim.x + threadIdx.x) >> 5;
    int lane = threadIdx.x & 31;
    if (n >= NN) return;
    int b = g_rowptr[n], e_ = g_rowptr[n + 1];
    if (b == e_) return;
    float m0 = -3.4e38f, m1 = -3.4e38f;
    for (int j = b + lane; j < e_; j += 32) {
        int e = g_eid[j];
        m0 = fmaxf(m0, g_alpha[2 * (size_t)e]);
        m1 = fmaxf(m1, g_alpha[2 * (size_t)e + 1]);
    }
#pragma unroll
    for (int o = 16; o; o >>= 1) {
        m0 = fmaxf(m0, __shfl_xor_sync(0xffffffffu, m0, o));
        m1 = fmaxf(m1, __shfl_xor_sync(0xffffffffu, m1, o));
    }
    float s0 = 0.f, s1 = 0.f;
    for (int j = b + lane; j < e_; j += 32) {
        int e = g_eid[j];
        s0 += expf(g_alpha[2 * (size_t)e]     - m0);
        s1 += expf(g_alpha[2 * (size_t)e + 1] - m1);
    }
#pragma unroll
    for (int o = 16; o; o >>= 1) {
        s0 += __shfl_xor_sync(0xffffffffu, s0, o);
        s1 += __shfl_xor_sync(0xffffffffu, s1, o);
    }
    float d0 = s0 + 1e-16f, d1 = s1 + 1e-16f;
    for (int j = b + lane; j < e_; j += 32) {
        int e = g_eid[j];
        float a0 = expf(g_alpha[2 * (size_t)e]     - m0) / d0;
        float a1 = expf(g_alpha[2 * (size_t)e + 1] - m1) / d1;
        g_alpha[2 * (size_t)e]     = a0;
        g_alpha[2 * (size_t)e + 1] = a1;
    }
}

// ---------------- aggregation: warp per node -> vagg (g_agg) + s (g_s) ----------------
__global__ void k_agg(const int* __restrict__ src) {
    int n = (blockIdx.x * blockDim.x + threadIdx.x) >> 5;
    int lane = threadIdx.x & 31;
    if (n >= NN) return;
    int b = g_rowptr[n], e_ = g_rowptr[n + 1];
    float vacc[8];
    float sacc[13];
#pragma unroll
    for (int i = 0; i < 8; i++) vacc[i] = 0.f;
#pragma unroll
    for (int i = 0; i < 13; i++) sacc[i] = 0.f;

    for (int j = b; j < e_; j++) {
        int e = g_eid[j];
        int s = src[e];
        float a0 = g_alpha[2 * (size_t)e];
        float a1 = g_alpha[2 * (size_t)e + 1];
        const float* vr = g_qkvs + (size_t)s * 1024 + 512;
#pragma unroll
        for (int k2 = 0; k2 < 8; k2++) {
            int cc = lane + 32 * k2;
            vacc[k2] += (cc < CC ? a0 : a1) * vr[cc];
        }
        const float* er = g_eattr + (size_t)e * ED;
#pragma unroll
        for (int k2 = 0; k2 < 13; k2++) {
            int dd = lane + 32 * k2;
            if (dd < 2 * ED) {
                int hh = (dd >= ED);
                int d_ = dd - hh * ED;
                sacc[k2] += (hh ? a1 : a0) * er[d_];
            }
        }
    }
    float* ar = g_agg + (size_t)n * INC;
#pragma unroll
    for (int k2 = 0; k2 < 8; k2++) ar[lane + 32 * k2] = vacc[k2];
    float* sr = g_s + (size_t)n * (2 * ED);
#pragma unroll
    for (int k2 = 0; k2 < 13; k2++) {
        int dd = lane + 32 * k2;
        if (dd < 2 * ED) sr[dd] = sacc[k2];
    }
}

// ---------------- residual + LayerNorm (+ SiLU) ----------------
__global__ void k_ln(const float* __restrict__ ln_g, const float* __restrict__ ln_b,
                     float* __restrict__ out, int silu) {
    int n = blockIdx.x;
    int c = threadIdx.x;
    size_t off = (size_t)n * INC + c;
    float pre = g_h[off] + g_agg[off] + g_qkvs[(size_t)n * 1024 + 768 + c];
    __shared__ float red[INC];
    red[c] = pre;
    __syncthreads();
#pragma unroll
    for (int o = 128; o; o >>= 1) {
        if (c < o) red[c] += red[c + o];
        __syncthreads();
    }
    float mu = red[0] * (1.f / INC);
    __syncthreads();
    float dv = pre - mu;
    red[c] = dv * dv;
    __syncthreads();
#pragma unroll
    for (int o = 128; o; o >>= 1) {
        if (c < o) red[c] += red[c + o];
        __syncthreads();
    }
    float var = red[0] * (1.f / INC);
    float y = dv * rsqrtf(var + 1e-5f) * ln_g[c] + ln_b[c];
    if (silu) y = y / (1.f + expf(-y));
    out[off] = y;
}

// ---------------- host launcher ----------------
static inline void get_sym(void** p, const void* sym) { cudaGetSymbolAddress(p, sym); }

extern "C" void kernel_launch(void* const* d_in, const int* in_sizes, int n_in,
                              void* d_out, int out_size) {
    const float* x           = (const float*)d_in[0];
    const float* last_update = (const float*)d_in[1];
    const int*   edge_index  = (const int*)  d_in[2];
    const float* t           = (const float*)d_in[3];
    const float* msg         = (const float*)d_in[4];
    const float* time_w      = (const float*)d_in[5];
    const float* time_b      = (const float*)d_in[6];
    const float* lin_w       = (const float*)d_in[7];
    const float* lin_b       = (const float*)d_in[8];
    const float* Wq          = (const float*)d_in[9];
    const float* bq          = (const float*)d_in[10];
    const float* Wk          = (const float*)d_in[11];
    const float* bk          = (const float*)d_in[12];
    const float* Wv          = (const float*)d_in[13];
    const float* bv          = (const float*)d_in[14];
    const float* We          = (const float*)d_in[15];
    const float* Wsk         = (const float*)d_in[16];
    const float* bsk         = (const float*)d_in[17];
    const float* ln_g        = (const float*)d_in[18];
    const float* ln_b        = (const float*)d_in[19];

    const int* src = edge_index;
    const int* dst = edge_index + EE;

    float *p_h, *p_qkvs, *p_U, *p_s, *p_agg, *p_WT, *p_bp, *p_linT, *p_WeT;
    get_sym((void**)&p_h,    g_h);
    get_sym((void**)&p_qkvs, g_qkvs);
    get_sym((void**)&p_U,    g_U);
    get_sym((void**)&p_s,    g_s);
    get_sym((void**)&p_agg,  g_agg);
    get_sym((void**)&p_WT,   g_WTpack);
    get_sym((void**)&p_bp,   g_bpack);
    get_sym((void**)&p_linT, g_linT);
    get_sym((void**)&p_WeT,  g_WeT);

    // ---- prep + CSR + edge features ----
    k_prep<<<512, 256>>>(Wq, Wk, Wv, Wsk, bq, bk, bv, bsk, lin_w, We);
    k_zero_int<<<(NN + 255) / 256, 256>>>();
    k_count<<<(EE + 255) / 256, 256>>>(dst);
    k_scan<<<1, 1024>>>();
    k_place<<<(EE + 255) / 256, 256>>>(dst);
    {
        long long total = (long long)EE * ED;
        k_eattr<<<(int)((total + 255) / 256), 256>>>(src, last_update, t, msg, time_w, time_b);
    }

    const int MT = (NN + 127) / 128;  // 157

    // ---- h0 = x @ lin_w + lin_b ----
    tc_gemm<<<dim3(2, MT), 256>>>(NN, INC, MEM, x, MEM, p_linT, MEM, lin_b, p_h, INC, 0);

    for (int L = 0; L < NLAYER; L++) {
        const float* We_i = We + (size_t)L * ED * INC;

        // fused q|k|v|sk projection: [NN,1024] = h @ WTpack^T
        tc_gemm<<<dim3(8, MT), 256>>>(
            NN, 1024, INC, p_h, INC,
            p_WT + (size_t)L * 1024 * 256, 256,
            p_bp + (size_t)L * 1024, p_qkvs, 1024, 0);

        // U[n,h,:] = q_h @ We_h^T  (B[n=j,k=c] = We[j, h*128+c])
        for (int h = 0; h < HH; h++) {
            tc_gemm<<<dim3(2, MT), 256>>>(
                NN, ED, CC,
                p_qkvs + h * CC, 1024,
                We_i + h * CC, INC,
                nullptr, p_U + h * ED, 2 * ED, 0);
        }

        k_alpha<<<(EE * 32 + 255) / 256, 256>>>(src, dst);
        k_softmax<<<(NN * 32 + 255) / 256, 256>>>();
        k_agg<<<(NN * 32 + 255) / 256, 256>>>(src);

        // agg[:, h*128:] += s_h @ We_h  (B[n=c,k=j] = WeT[L][h*128+c][j])
        for (int h = 0; h < HH; h++) {
            tc_gemm<<<dim3(1, MT), 256>>>(
                NN, CC, ED,
                p_s + h * ED, 2 * ED,
                p_WeT + (size_t)L * 256 * 200 + (size_t)(h * CC) * 200, 200,
                nullptr, p_agg + h * CC, INC, 1);
        }

        float* out_ptr = (L == NLAYER - 1) ? (float*)d_out : p_h;
        k_ln<<<NN, INC>>>(ln_g + (size_t)L * INC, ln_b + (size_t)L * INC,
                          out_ptr, (L < NLAYER - 1) ? 1 : 0);
    }
}

// round 4
// speedup vs baseline: 2.1071x; 1.3177x over previous
#include <cuda_runtime.h>
#include <cuda_bf16.h>
#include <math.h>
#include <float.h>
#include <stdint.h>

// ---------------- problem constants ----------------
#define NN 20000
#define EE 320000
#define MEM 128
#define INC 256
#define HH 2
#define CC 128
#define ED 200
#define TD 100
#define NLAYER 3

static __device__ __constant__ float RSQRT_C = 0.08838834764831845f; // 1/sqrt(128)

// ---------------- scratch ----------------
__device__ float g_te   [(size_t)EE * TD];       // 128 MB: time-encoding half of eattr
__device__ float g_h    [(size_t)NN * INC];
__device__ float g_qkvs [(size_t)NN * 1024];     // q|k|v|sk packed
__device__ float g_U    [(size_t)NN * 2 * ED];
__device__ float g_s    [(size_t)NN * 2 * ED];
__device__ float g_agg  [(size_t)NN * INC];
__device__ int   g_deg [NN];
__device__ int   g_cnt [NN];
__device__ int   g_rowptr[NN + 1];
__device__ int   g_eid [EE];
// packed / transposed weights
__device__ float g_WTpack[(size_t)NLAYER * 1024 * 256];  // [L][n(q,k,v,sk)][k]
__device__ float g_bpack [(size_t)NLAYER * 1024];
__device__ float g_linT  [(size_t)256 * 128];            // lin_w^T
__device__ float g_WeT   [(size_t)NLAYER * 256 * 200];   // We^T: [L][c][j]

// ---------------- bf16 split helpers ----------------
__device__ __forceinline__ uint32_t pack_hi(float x, float y) {
    __nv_bfloat162 p = __floats2bfloat162_rn(x, y);
    return *(uint32_t*)&p;
}
__device__ __forceinline__ uint32_t pack_mid(float x, float y) {
    __nv_bfloat16 hx = __float2bfloat16(x);
    __nv_bfloat16 hy = __float2bfloat16(y);
    __nv_bfloat162 p = __floats2bfloat162_rn(x - __bfloat162float(hx),
                                             y - __bfloat162float(hy));
    return *(uint32_t*)&p;
}
__device__ __forceinline__ void mma_bf16(float* c, const uint32_t* a,
                                         uint32_t b0, uint32_t b1) {
    asm volatile(
        "mma.sync.aligned.m16n8k16.row.col.f32.bf16.bf16.f32 "
        "{%0,%1,%2,%3}, {%4,%5,%6,%7}, {%8,%9}, {%0,%1,%2,%3};"
        : "+f"(c[0]), "+f"(c[1]), "+f"(c[2]), "+f"(c[3])
        : "r"(a[0]), "r"(a[1]), "r"(a[2]), "r"(a[3]), "r"(b0), "r"(b1));
}

// ---------------- HMMA 3xBF16 GEMM, software-pipelined ----------------
// C[M,N] (+)= A[M,K] @ B^T[N,K]. A row-major [M,lda]; B row-major [N,ldb];
// optional bias[n]; optional accum. Tile 128x128, BK=32, 256 thr (8 warps 4x2).
#define PADU 17

__global__ __launch_bounds__(256, 1)
void tc_gemm(int M, int N, int K,
             const float* __restrict__ A, int lda,
             const float* __restrict__ B, int ldb,
             const float* __restrict__ bias,
             float* __restrict__ C, int ldc,
             int accum) {
    __shared__ uint32_t As_h[128 * PADU];
    __shared__ uint32_t As_m[128 * PADU];
    __shared__ uint32_t Bs_h[128 * PADU];
    __shared__ uint32_t Bs_m[128 * PADU];

    const int tid = threadIdx.x;
    const int wid = tid >> 5;
    const int lane = tid & 31;
    const int wm = wid & 3;
    const int wn = wid >> 2;
    const int m0 = blockIdx.y * 128;
    const int n0 = blockIdx.x * 128;

    const int lr = tid >> 3;            // load row 0..127 (per 256-thr pass: 32 rows? no: id>>3)
    float c[2][8][4];
#pragma unroll
    for (int i = 0; i < 2; i++)
#pragma unroll
        for (int j = 0; j < 8; j++)
#pragma unroll
            for (int l = 0; l < 4; l++) c[i][j][l] = 0.f;

    float4 aR[4], bR[4];
    const int nc = (K + 31) >> 5;

#define LOADAB(K0)                                                        \
    do {                                                                  \
        _Pragma("unroll")                                                 \
        for (int it = 0; it < 4; it++) {                                  \
            int id = tid + it * 256;                                      \
            int r = id >> 3, c4 = (id & 7) * 4;                           \
            int gk = (K0) + c4;                                           \
            int gm = m0 + r, gn = n0 + r;                                 \
            aR[it] = (gm < M && gk < K)                                   \
                ? *(const float4*)(A + (size_t)gm * lda + gk)             \
                : make_float4(0.f, 0.f, 0.f, 0.f);                        \
            bR[it] = (gn < N && gk < K)                                   \
                ? *(const float4*)(B + (size_t)gn * ldb + gk)             \
                : make_float4(0.f, 0.f, 0.f, 0.f);                        \
        }                                                                 \
    } while (0)

    LOADAB(0);

    for (int ch = 0; ch < nc; ch++) {
        // ---- convert + store current regs to smem ----
#pragma unroll
        for (int it = 0; it < 4; it++) {
            int id = tid + it * 256;
            int r = id >> 3, c4 = (id & 7) * 4;
            int base = r * PADU + (c4 >> 1);
            float4 v = aR[it];
            As_h[base]     = pack_hi(v.x, v.y);
            As_h[base + 1] = pack_hi(v.z, v.w);
            As_m[base]     = pack_mid(v.x, v.y);
            As_m[base + 1] = pack_mid(v.z, v.w);
            v = bR[it];
            Bs_h[base]     = pack_hi(v.x, v.y);
            Bs_h[base + 1] = pack_hi(v.z, v.w);
            Bs_m[base]     = pack_mid(v.x, v.y);
            Bs_m[base + 1] = pack_mid(v.z, v.w);
        }
        __syncthreads();
        // ---- issue next chunk's loads (latency overlaps compute) ----
        if (ch + 1 < nc) LOADAB((ch + 1) << 5);

        // ---- compute ----
#pragma unroll
        for (int ks = 0; ks < 2; ks++) {
            const int kc = ks * 8 + (lane & 3);
            uint32_t ah[2][4], am[2][4];
#pragma unroll
            for (int mt = 0; mt < 2; mt++) {
                int r0 = (wm * 32 + mt * 16 + (lane >> 2)) * PADU;
                int r1 = r0 + 8 * PADU;
                ah[mt][0] = As_h[r0 + kc];
                ah[mt][1] = As_h[r1 + kc];
                ah[mt][2] = As_h[r0 + kc + 4];
                ah[mt][3] = As_h[r1 + kc + 4];
                am[mt][0] = As_m[r0 + kc];
                am[mt][1] = As_m[r1 + kc];
                am[mt][2] = As_m[r0 + kc + 4];
                am[mt][3] = As_m[r1 + kc + 4];
            }
#pragma unroll
            for (int nt = 0; nt < 8; nt++) {
                int nb = (wn * 64 + nt * 8 + (lane >> 2)) * PADU;
                uint32_t bh0 = Bs_h[nb + kc];
                uint32_t bh1 = Bs_h[nb + kc + 4];
                uint32_t bm0 = Bs_m[nb + kc];
                uint32_t bm1 = Bs_m[nb + kc + 4];
#pragma unroll
                for (int mt = 0; mt < 2; mt++) {
                    mma_bf16(c[mt][nt], ah[mt], bh0, bh1);
                    mma_bf16(c[mt][nt], ah[mt], bm0, bm1);
                    mma_bf16(c[mt][nt], am[mt], bh0, bh1);
                }
            }
        }
        __syncthreads();
    }
#undef LOADAB

    // ---- epilogue ----
#pragma unroll
    for (int mt = 0; mt < 2; mt++) {
        int row0 = m0 + wm * 32 + mt * 16 + (lane >> 2);
#pragma unroll
        for (int nt = 0; nt < 8; nt++) {
            int col = n0 + wn * 64 + nt * 8 + 2 * (lane & 3);
            if (col >= N) continue;
#pragma unroll
            for (int half = 0; half < 2; half++) {
                int row = row0 + 8 * half;
                if (row >= M) continue;
                float v0 = c[mt][nt][2 * half];
                float v1 = c[mt][nt][2 * half + 1];
                if (bias) { v0 += bias[col]; v1 += (col + 1 < N) ? bias[col + 1] : 0.f; }
                size_t off = (size_t)row * ldc + col;
                if (accum) {
                    v0 += C[off];
                    if (col + 1 < N) v1 += C[off + 1];
                }
                C[off] = v0;
                if (col + 1 < N) C[off + 1] = v1;
            }
        }
    }
}

// ---------------- weight prep ----------------
__global__ void k_prep(const float* __restrict__ Wq, const float* __restrict__ Wk,
                       const float* __restrict__ Wv, const float* __restrict__ Wsk,
                       const float* __restrict__ bq, const float* __restrict__ bk,
                       const float* __restrict__ bv, const float* __restrict__ bsk,
                       const float* __restrict__ lin_w, const float* __restrict__ We) {
    const int A1 = NLAYER * 1024 * 256;
    const int A2 = NLAYER * 1024;
    const int A3 = 256 * 128;
    const int A4 = NLAYER * 256 * 200;
    int total = A1 + A2 + A3 + A4;
    for (int idx = blockIdx.x * blockDim.x + threadIdx.x; idx < total;
         idx += gridDim.x * blockDim.x) {
        if (idx < A1) {
            int L = idx / (1024 * 256);
            int rem = idx - L * 1024 * 256;
            int row = rem >> 8;
            int k = rem & 255;
            int which = row >> 8;
            int n = row & 255;
            const float* W = (which == 0) ? Wq : (which == 1) ? Wk : (which == 2) ? Wv : Wsk;
            g_WTpack[idx] = W[(size_t)L * 65536 + (size_t)k * 256 + n];
        } else if (idx < A1 + A2) {
            int i2 = idx - A1;
            int L = i2 / 1024;
            int row = i2 - L * 1024;
            int which = row >> 8;
            int n = row & 255;
            const float* bb = (which == 0) ? bq : (which == 1) ? bk : (which == 2) ? bv : bsk;
            g_bpack[i2] = bb[L * 256 + n];
        } else if (idx < A1 + A2 + A3) {
            int i3 = idx - A1 - A2;
            int n = i3 >> 7, k = i3 & 127;
            g_linT[i3] = lin_w[(size_t)k * 256 + n];
        } else {
            int i4 = idx - A1 - A2 - A3;
            int L = i4 / (256 * 200);
            int rem = i4 - L * 256 * 200;
            int c = rem / 200;
            int j = rem - c * 200;
            g_WeT[i4] = We[(size_t)L * 51200 + (size_t)j * 256 + c];
        }
    }
}

// ---------------- CSR construction ----------------
__global__ void k_zero_int() {
    int i = blockIdx.x * blockDim.x + threadIdx.x;
    if (i < NN) { g_deg[i] = 0; g_cnt[i] = 0; }
}
__global__ void k_count(const int* __restrict__ dst) {
    int e = blockIdx.x * blockDim.x + threadIdx.x;
    if (e < EE) atomicAdd(&g_deg[dst[e]], 1);
}
__global__ void k_scan() {
    __shared__ int wsum[32];
    int tid = threadIdx.x;
    int lane = tid & 31;
    int wid = tid >> 5;
    int carry = 0;
    for (int base = 0; base < NN; base += 1024) {
        int i = base + tid;
        int x = (i < NN) ? g_deg[i] : 0;
#pragma unroll
        for (int o = 1; o < 32; o <<= 1) {
            int y = __shfl_up_sync(0xffffffffu, x, o);
            if (lane >= o) x += y;
        }
        if (lane == 31) wsum[wid] = x;
        __syncthreads();
        if (wid == 0) {
            int s = wsum[lane];
#pragma unroll
            for (int o = 1; o < 32; o <<= 1) {
                int y = __shfl_up_sync(0xffffffffu, s, o);
                if (lane >= o) s += y;
            }
            wsum[lane] = s;
        }
        __syncthreads();
        int off = (wid > 0) ? wsum[wid - 1] : 0;
        if (i < NN) g_rowptr[i + 1] = carry + off + x;
        carry += wsum[31];
        __syncthreads();
    }
    if (tid == 0) g_rowptr[0] = 0;
}
__global__ void k_place(const int* __restrict__ dst) {
    int e = blockIdx.x * blockDim.x + threadIdx.x;
    if (e < EE) {
        int d = dst[e];
        int p = atomicAdd(&g_cnt[d], 1);
        g_eid[g_rowptr[d] + p] = e;
    }
}

// ---------------- time-encoding features (cos half of eattr) ----------------
__global__ void k_te(const int* __restrict__ src,
                     const float* __restrict__ last_update,
                     const float* __restrict__ t,
                     const float* __restrict__ time_w,
                     const float* __restrict__ time_b) {
    long long idx = (long long)blockIdx.x * blockDim.x + threadIdx.x;
    long long total = (long long)EE * TD;
    if (idx >= total) return;
    int e = (int)(idx / TD);
    int j = (int)(idx - (long long)e * TD);
    float rt = last_update[src[e]] - t[e];
    g_te[idx] = cosf(rt * time_w[j] + time_b[j]);
}

// ---------------- fused edge phase: alpha + online softmax + aggregation ----------------
// warp per destination node; produces g_agg (v-part, already normalized) and g_s.
__global__ __launch_bounds__(256)
void k_edge(const int* __restrict__ src, const float* __restrict__ msg) {
    int n = (blockIdx.x * blockDim.x + threadIdx.x) >> 5;
    int lane = threadIdx.x & 31;
    if (n >= NN) return;
    int b = g_rowptr[n], e_ = g_rowptr[n + 1];

    // per-node operands
    float q[8];
    const float* qr = g_qkvs + (size_t)n * 1024;
#pragma unroll
    for (int i = 0; i < 8; i++) q[i] = qr[lane + 32 * i];
    float u0[7], u1[7];
    const float* Ur = g_U + (size_t)n * (2 * ED);
#pragma unroll
    for (int i = 0; i < 7; i++) {
        int j = lane + 32 * i;
        u0[i] = (j < ED) ? Ur[j] : 0.f;
        u1[i] = (j < ED) ? Ur[ED + j] : 0.f;
    }

    float m0 = -FLT_MAX, m1 = -FLT_MAX, d0 = 0.f, d1 = 0.f;
    float vacc[8], s0[7], s1[7];
#pragma unroll
    for (int i = 0; i < 8; i++) vacc[i] = 0.f;
#pragma unroll
    for (int i = 0; i < 7; i++) { s0[i] = 0.f; s1[i] = 0.f; }

    for (int jj = b; jj < e_; jj++) {
        int e = g_eid[jj];
        int sN = src[e];
        const float* kr = g_qkvs + (size_t)sN * 1024 + 256;
        const float* vr = kr + 256;
        float kv[8], vv[8], er[7];
#pragma unroll
        for (int i = 0; i < 8; i++) { kv[i] = kr[lane + 32 * i]; vv[i] = vr[lane + 32 * i]; }
        const float* te = g_te + (size_t)e * TD;
        const float* mg = msg + (size_t)e * TD;
#pragma unroll
        for (int i = 0; i < 7; i++) {
            int j = lane + 32 * i;
            er[i] = (j < ED) ? ((j < TD) ? te[j] : mg[j - TD]) : 0.f;
        }
        float a0 = 0.f, a1 = 0.f;
#pragma unroll
        for (int i = 0; i < 4; i++) { a0 += q[i] * kv[i]; a1 += q[i + 4] * kv[i + 4]; }
#pragma unroll
        for (int i = 0; i < 7; i++) { a0 += er[i] * u0[i]; a1 += er[i] * u1[i]; }
#pragma unroll
        for (int o = 16; o; o >>= 1) {
            a0 += __shfl_xor_sync(0xffffffffu, a0, o);
            a1 += __shfl_xor_sync(0xffffffffu, a1, o);
        }
        a0 *= RSQRT_C;
        a1 *= RSQRT_C;

        float mn0 = fmaxf(m0, a0);
        float sc0 = expf(m0 - mn0);
        float w0 = expf(a0 - mn0);
        d0 = d0 * sc0 + w0;
        m0 = mn0;
        float mn1 = fmaxf(m1, a1);
        float sc1 = expf(m1 - mn1);
        float w1 = expf(a1 - mn1);
        d1 = d1 * sc1 + w1;
        m1 = mn1;
#pragma unroll
        for (int i = 0; i < 4; i++) {
            vacc[i]     = vacc[i]     * sc0 + w0 * vv[i];
            vacc[i + 4] = vacc[i + 4] * sc1 + w1 * vv[i + 4];
        }
#pragma unroll
        for (int i = 0; i < 7; i++) {
            s0[i] = s0[i] * sc0 + w0 * er[i];
            s1[i] = s1[i] * sc1 + w1 * er[i];
        }
    }

    float div0 = 1.f / (d0 + 1e-16f);
    float div1 = 1.f / (d1 + 1e-16f);
    float* ar = g_agg + (size_t)n * INC;
#pragma unroll
    for (int i = 0; i < 4; i++) {
        ar[lane + 32 * i]       = vacc[i] * div0;
        ar[lane + 32 * (i + 4)] = vacc[i + 4] * div1;
    }
    float* sr = g_s + (size_t)n * (2 * ED);
#pragma unroll
    for (int i = 0; i < 7; i++) {
        int j = lane + 32 * i;
        if (j < ED) {
            sr[j]      = s0[i] * div0;
            sr[ED + j] = s1[i] * div1;
        }
    }
}

// ---------------- residual + LayerNorm (+ SiLU) ----------------
__global__ void k_ln(const float* __restrict__ ln_g, const float* __restrict__ ln_b,
                     float* __restrict__ out, int silu) {
    int n = blockIdx.x;
    int c = threadIdx.x;
    size_t off = (size_t)n * INC + c;
    float pre = g_h[off] + g_agg[off] + g_qkvs[(size_t)n * 1024 + 768 + c];
    __shared__ float red[INC];
    red[c] = pre;
    __syncthreads();
#pragma unroll
    for (int o = 128; o; o >>= 1) {
        if (c < o) red[c] += red[c + o];
        __syncthreads();
    }
    float mu = red[0] * (1.f / INC);
    __syncthreads();
    float dv = pre - mu;
    red[c] = dv * dv;
    __syncthreads();
#pragma unroll
    for (int o = 128; o; o >>= 1) {
        if (c < o) red[c] += red[c + o];
        __syncthreads();
    }
    float var = red[0] * (1.f / INC);
    float y = dv * rsqrtf(var + 1e-5f) * ln_g[c] + ln_b[c];
    if (silu) y = y / (1.f + expf(-y));
    out[off] = y;
}

// ---------------- host launcher ----------------
static inline void get_sym(void** p, const void* sym) { cudaGetSymbolAddress(p, sym); }

extern "C" void kernel_launch(void* const* d_in, const int* in_sizes, int n_in,
                              void* d_out, int out_size) {
    const float* x           = (const float*)d_in[0];
    const float* last_update = (const float*)d_in[1];
    const int*   edge_index  = (const int*)  d_in[2];
    const float* t           = (const float*)d_in[3];
    const float* msg         = (const float*)d_in[4];
    const float* time_w      = (const float*)d_in[5];
    const float* time_b      = (const float*)d_in[6];
    const float* lin_w       = (const float*)d_in[7];
    const float* lin_b       = (const float*)d_in[8];
    const float* Wq          = (const float*)d_in[9];
    const float* bq          = (const float*)d_in[10];
    const float* Wk          = (const float*)d_in[11];
    const float* bk          = (const float*)d_in[12];
    const float* Wv          = (const float*)d_in[13];
    const float* bv          = (const float*)d_in[14];
    const float* We          = (const float*)d_in[15];
    const float* Wsk         = (const float*)d_in[16];
    const float* bsk         = (const float*)d_in[17];
    const float* ln_g        = (const float*)d_in[18];
    const float* ln_b        = (const float*)d_in[19];

    const int* src = edge_index;
    const int* dst = edge_index + EE;

    float *p_h, *p_qkvs, *p_U, *p_s, *p_agg, *p_WT, *p_bp, *p_linT, *p_WeT;
    get_sym((void**)&p_h,    g_h);
    get_sym((void**)&p_qkvs, g_qkvs);
    get_sym((void**)&p_U,    g_U);
    get_sym((void**)&p_s,    g_s);
    get_sym((void**)&p_agg,  g_agg);
    get_sym((void**)&p_WT,   g_WTpack);
    get_sym((void**)&p_bp,   g_bpack);
    get_sym((void**)&p_linT, g_linT);
    get_sym((void**)&p_WeT,  g_WeT);

    // ---- prep + CSR + time-encoding features ----
    k_prep<<<512, 256>>>(Wq, Wk, Wv, Wsk, bq, bk, bv, bsk, lin_w, We);
    k_zero_int<<<(NN + 255) / 256, 256>>>();
    k_count<<<(EE + 255) / 256, 256>>>(dst);
    k_scan<<<1, 1024>>>();
    k_place<<<(EE + 255) / 256, 256>>>(dst);
    {
        long long total = (long long)EE * TD;
        k_te<<<(int)((total + 255) / 256), 256>>>(src, last_update, t, time_w, time_b);
    }

    const int MT = (NN + 127) / 128;  // 157

    // ---- h0 = x @ lin_w + lin_b ----
    tc_gemm<<<dim3(2, MT), 256>>>(NN, INC, MEM, x, MEM, p_linT, MEM, lin_b, p_h, INC, 0);

    for (int L = 0; L < NLAYER; L++) {
        const float* We_i = We + (size_t)L * ED * INC;

        // fused q|k|v|sk projection: [NN,1024] = h @ WTpack^T
        tc_gemm<<<dim3(8, MT), 256>>>(
            NN, 1024, INC, p_h, INC,
            p_WT + (size_t)L * 1024 * 256, 256,
            p_bp + (size_t)L * 1024, p_qkvs, 1024, 0);

        // U[n,h,:] = q_h @ We_h^T
        for (int h = 0; h < HH; h++) {
            tc_gemm<<<dim3(2, MT), 256>>>(
                NN, ED, CC,
                p_qkvs + h * CC, 1024,
                We_i + h * CC, INC,
                nullptr, p_U + h * ED, 2 * ED, 0);
        }

        // fused alpha + online softmax + aggregation
        k_edge<<<(NN * 32 + 255) / 256, 256>>>(src, msg);

        // agg[:, h*128:] += s_h @ We_h
        for (int h = 0; h < HH; h++) {
            tc_gemm<<<dim3(1, MT), 256>>>(
                NN, CC, ED,
                p_s + h * ED, 2 * ED,
                p_WeT + (size_t)L * 256 * 200 + (size_t)(h * CC) * 200, 200,
                nullptr, p_agg + h * CC, INC, 1);
        }

        float* out_ptr = (L == NLAYER - 1) ? (float*)d_out : p_h;
        k_ln<<<NN, INC>>>(ln_g + (size_t)L * INC, ln_b + (size_t)L * INC,
                          out_ptr, (L < NLAYER - 1) ? 1 : 0);
    }
}